// round 15
// baseline (speedup 1.0000x reference)
#include <cuda_runtime.h>
#include <cuda_bf16.h>
#include <cuda_fp16.h>
#include <math.h>

#define Hh 128
#define Rr 50
#define Ll 4
#define Nn 10000
#define Mm 64
#define NP 10112           // 79 * 128
#define EMAX 2000000
#define BINS 2048
#define SCALE ((float)BINS / 5.0f)
#define STEP (5.0f / (float)BINS)
#define TBB 64

typedef unsigned long long u64;
typedef unsigned int u32;

__device__ __forceinline__ void fma2(u64 &d, u64 a, u64 b) {
    asm("fma.rn.f32x2 %0, %1, %2, %0;" : "+l"(d) : "l"(a), "l"(b));
}
__device__ __forceinline__ u64 pack2(float lo, float hi) {
    u64 r; asm("mov.b64 %0, {%1, %2};" : "=l"(r) : "f"(lo), "f"(hi)); return r;
}
__device__ __forceinline__ void unpack2(u64 v, float &lo, float &hi) {
    asm("mov.b64 {%0, %1}, %2;" : "=f"(lo), "=f"(hi) : "l"(v));
}
__device__ __forceinline__ float tanhap(float x) {
    float r; asm("tanh.approx.f32 %0, %1;" : "=f"(r) : "f"(x)); return r;
}

__device__ __forceinline__ float gru_upd(float xo, float rv, float zv, float nv,
                                         float bhr, float bhz, float bhn) {
    float r = __fdividef(1.f, 1.f + __expf(-(rv + bhr)));
    float z = __fdividef(1.f, 1.f + __expf(-(zv + bhz)));
    float t = nv + r * bhn;
    float e = __expf(2.f * t);
    float th = 1.f - __fdividef(2.f, e + 1.f);
    return xo + (1.f - z) * th;
}

__device__ __forceinline__ void mma16816(float* d, const u32* a, u32 b0, u32 b1) {
    asm volatile(
        "mma.sync.aligned.m16n8k16.row.col.f32.bf16.bf16.f32 "
        "{%0,%1,%2,%3}, {%4,%5,%6,%7}, {%8,%9}, {%0,%1,%2,%3};"
        : "+f"(d[0]), "+f"(d[1]), "+f"(d[2]), "+f"(d[3])
        : "r"(a[0]), "r"(a[1]), "r"(a[2]), "r"(a[3]), "r"(b0), "r"(b1));
}

// ---------------- scratch ----------------
__device__ float   g_x[NP * Hh];
__device__ __half  g_y[NP * Hh];
__device__ float   g_S[NP * Hh];
__device__ float   g_gi[NP * 3 * Hh];
__device__ float   g_d[EMAX];
__device__ int     g_rp[Nn + 1];
__device__ float   g_sums[Mm * Hh];
__device__ float   g_cnt[Mm];
__device__ __half2 g_tabh[Ll * BINS * Hh];
__device__ float   g_Wc[Ll * Hh * 3 * Hh];
__device__ float   g_bc2[Ll * 3 * Hh];
__device__ unsigned short g_imgY[Ll * 2 * 16384];
__device__ unsigned short g_imgG[Ll * 3 * 2 * 16384];
__device__ float   g_scr[NP * Hh];   // fp32 scratch for ln out when out_size small
__device__ int     g_ctr;

// smem byte offsets for mma_gemm (row stride 272B = 136 bf16)
#define SM_AH 0
#define SM_AL 34816
#define SM_BH 69632
#define SM_BL 104448
#define SM_MMA_TOT 139264

// ---------------- prep0 ----------------
__global__ void prep0(const int* __restrict__ an, const float* __restrict__ emb,
                      const int* __restrict__ rowp, int E,
                      float* __restrict__ x, float* __restrict__ sums,
                      float* __restrict__ cnt, int* __restrict__ rp) {
    int i = blockIdx.x * blockDim.x + threadIdx.x;
    if (i < NP * Hh) {
        int n = i >> 7, ch = i & 127;
        if (n < Nn) {
            int a = an[n];
            a = a < 0 ? 0 : (a > 99 ? 99 : a);
            x[i] = emb[a * Hh + ch];
        } else {
            x[i] = 0.f;
        }
        return;
    }
    int i2 = i - NP * Hh;
    if (i2 < Mm * Hh) { sums[i2] = 0.f; return; }
    i2 -= Mm * Hh;
    if (i2 < Mm) { cnt[i2] = 0.f; return; }
    int e = i2 - Mm;
    if (e > E) return;
    if (e == 0) {
        int b = rowp[0];
        for (int r = 0; r <= b; r++) rp[r] = 0;
    } else if (e == E) {
        int a = rowp[E - 1];
        for (int r = a + 1; r <= Nn; r++) rp[r] = E;
    } else {
        int a = rowp[e - 1], b = rowp[e];
        for (int r = a + 1; r <= b; r++) rp[r] = e;
    }
}

// ---------------- prep1: distances + fp16 table (tiled) + bc2 ----------------
__global__ void prep1(const float* __restrict__ pos, const int* __restrict__ rowp,
                      const int* __restrict__ colp, int E, int ndb,
                      const float* __restrict__ W1, const float* __restrict__ W_ih,
                      const float* __restrict__ b2,
                      float* __restrict__ dv, __half2* __restrict__ tab,
                      float* __restrict__ bc2) {
    __shared__ float basis[(TBB + 1) * Rr];
    int tid = threadIdx.x;
    int blk = blockIdx.x;
    if (blk < ndb) {
        int e = blk * 128 + tid;
        if (e < E) {
            int r = rowp[e], c = colp[e];
            float dx = pos[r * 3 + 0] - pos[c * 3 + 0];
            float dy = pos[r * 3 + 1] - pos[c * 3 + 1];
            float dz = pos[r * 3 + 2] - pos[c * 3 + 2];
            dv[e] = sqrtf(dx * dx + dy * dy + dz * dz);
        }
        return;
    }
    int t = blk - ndb;
    const int TBLKS = BINS / TBB;
    if (t < TBLKS * Ll) {
        int l = t / TBLKS, bt = t - l * TBLKS;
        int bin0 = bt * TBB;
        for (int i = tid; i < (TBB + 1) * Rr; i += 128) {
            int g = i / Rr, k = i - g * Rr;
            float c = (float)k * (5.0f / 49.0f);
            float d0 = (float)(bin0 + g) * STEP - c;
            basis[i] = expf(-50.0f * d0 * d0);
        }
        __syncthreads();
        const float* W1b = W1 + l * (Hh + Rr) * Hh + Hh * Hh;
        float w[Rr];
#pragma unroll
        for (int k = 0; k < Rr; k++) w[k] = W1b[k * Hh + tid];
        float vprev = 0.f;
#pragma unroll
        for (int k = 0; k < Rr; k++) vprev += basis[k] * w[k];
        for (int g = 1; g <= TBB; g++) {
            float v = 0.f;
            const float* bs = &basis[g * Rr];
#pragma unroll
            for (int k = 0; k < Rr; k++) v += bs[k] * w[k];
            tab[((l * BINS + bin0 + g - 1) << 7) + tid] = __floats2half2_rn(vprev, v - vprev);
            vprev = v;
        }
        return;
    }
    int t2 = t - TBLKS * Ll;
    int l = t2 / 3, chunk = t2 - l * 3;
    int n = chunk * 128 + tid;
    const float* W = W_ih + l * Hh * 3 * Hh;
    const float* b = b2 + l * Hh;
    float s = 0.f;
#pragma unroll 8
    for (int k = 0; k < Hh; k++) s += b[k] * W[k * 3 * Hh + n];
    bc2[l * 3 * Hh + n] = s;
}

// ---------------- prep2: transposed split bf16 weight planes [n][k], 128 blocks ----
__global__ void prep2(const float* __restrict__ W1, const float* __restrict__ Wc,
                      unsigned short* __restrict__ imgY, unsigned short* __restrict__ imgG) {
    int b = blockIdx.x, tid = threadIdx.x;
    int k0base = blockIdx.y * 16;
    const float* src;
    int srcNr, colOff;
    unsigned short* dst;
    if (b < 4) {
        src = W1 + (size_t)b * (Hh + Rr) * Hh;
        srcNr = 128; colOff = 0;
        dst = imgY + (size_t)b * 32768;
    } else {
        int t = b - 4;
        int l = t / 3, c = t - l * 3;
        src = Wc + (size_t)l * Hh * 384;
        srcNr = 384; colOff = c * 128;
        dst = imgG + (size_t)t * 32768;
    }
    for (int k0 = k0base; k0 < k0base + 16; k0 += 8) {
        unsigned short hi[8], lo[8];
#pragma unroll
        for (int e = 0; e < 8; e++) {
            float v = src[(size_t)(k0 + e) * srcNr + colOff + tid];
            __nv_bfloat16 h = __float2bfloat16(v);
            __nv_bfloat16 l2 = __float2bfloat16(v - __bfloat162float(h));
            hi[e] = *(unsigned short*)&h;
            lo[e] = *(unsigned short*)&l2;
        }
        *(uint4*)(dst + (size_t)tid * 128 + k0) = *(uint4*)hi;
        *(uint4*)(dst + 16384 + (size_t)tid * 128 + k0) = *(uint4*)lo;
    }
}

// ---------------- f32x2 GEMM (small Wc precompute only) ----------------
__global__ void __launch_bounds__(256, 2)
gemm_f2b(const float* __restrict__ A, const float* __restrict__ B,
         float* __restrict__ C, int Nr, int aSz, int bSz, int cSz) {
    __shared__ float As[16][132];
    __shared__ float Bs[16][128];
    int tid = threadIdx.x;
    int tx = tid & 15, ty = tid >> 4;
    int m0 = blockIdx.y * 128, n0 = blockIdx.x * 128;
    const float* Ab = A + (size_t)blockIdx.z * aSz;
    const float* Bb = B + (size_t)blockIdx.z * bSz;
    float* Cb = C + (size_t)blockIdx.z * cSz;
    u64 acc[4][8] = {};
    for (int kk = 0; kk < 128; kk += 16) {
#pragma unroll
        for (int it = 0; it < 2; it++) {
            int r = (tid >> 2) + it * 64;
            int c4 = (tid & 3) << 2;
            float4 v = *(const float4*)(Ab + (size_t)(m0 + r) * 128 + kk + c4);
            As[c4 + 0][r] = v.x; As[c4 + 1][r] = v.y;
            As[c4 + 2][r] = v.z; As[c4 + 3][r] = v.w;
        }
        {
            int r = tid >> 4, c8 = (tid & 15) << 3;
            *(float4*)&Bs[r][c8]     = *(const float4*)(Bb + (size_t)(kk + r) * Nr + n0 + c8);
            *(float4*)&Bs[r][c8 + 4] = *(const float4*)(Bb + (size_t)(kk + r) * Nr + n0 + c8 + 4);
        }
        __syncthreads();
#pragma unroll
        for (int k = 0; k < 16; k++) {
            longlong2 la = *(const longlong2*)&As[k][ty * 8];
            longlong2 lb = *(const longlong2*)&As[k][ty * 8 + 4];
            float4 b0 = *(const float4*)&Bs[k][tx * 8];
            float4 b1 = *(const float4*)&Bs[k][tx * 8 + 4];
            u64 ap[4] = { (u64)la.x, (u64)la.y, (u64)lb.x, (u64)lb.y };
            u64 bp[8] = { pack2(b0.x, b0.x), pack2(b0.y, b0.y),
                          pack2(b0.z, b0.z), pack2(b0.w, b0.w),
                          pack2(b1.x, b1.x), pack2(b1.y, b1.y),
                          pack2(b1.z, b1.z), pack2(b1.w, b1.w) };
#pragma unroll
            for (int i = 0; i < 4; i++)
#pragma unroll
                for (int j = 0; j < 8; j++) fma2(acc[i][j], ap[i], bp[j]);
        }
        __syncthreads();
    }
#pragma unroll
    for (int i = 0; i < 4; i++) {
        int mA = m0 + ty * 8 + 2 * i;
        float lo[8], hi[8];
#pragma unroll
        for (int j = 0; j < 8; j++) unpack2(acc[i][j], lo[j], hi[j]);
        *(float4*)(Cb + (size_t)mA * Nr + n0 + tx * 8)     = make_float4(lo[0], lo[1], lo[2], lo[3]);
        *(float4*)(Cb + (size_t)mA * Nr + n0 + tx * 8 + 4) = make_float4(lo[4], lo[5], lo[6], lo[7]);
        *(float4*)(Cb + (size_t)(mA + 1) * Nr + n0 + tx * 8)     = make_float4(hi[0], hi[1], hi[2], hi[3]);
        *(float4*)(Cb + (size_t)(mA + 1) * Nr + n0 + tx * 8 + 4) = make_float4(hi[4], hi[5], hi[6], hi[7]);
    }
}

// ---------------- split-bf16 mma.sync GEMM, tile 128x128, fused GRU prologue --------
// If Ch != null, the result is stored as fp16 to Ch; otherwise fp32 to C.
__global__ void __launch_bounds__(256)
mma_gemm(const float* __restrict__ A, const unsigned short* __restrict__ Bimg,
         const float* __restrict__ bias, const int* __restrict__ rp,
         const float* __restrict__ bias2,
         const float* __restrict__ gi, const float* __restrict__ bhh,
         float* __restrict__ xout, float* __restrict__ C,
         __half* __restrict__ Ch, int Nr) {
    extern __shared__ char sm[];
    int tid = threadIdx.x;
    int lane = tid & 31, wid = tid >> 5;
    int wm = wid >> 1, wn = wid & 1;
    int gid = lane >> 2, tig = lane & 3;
    int m0 = blockIdx.y * 128, n0 = blockIdx.x * 128;

    {
        const unsigned short* srcH = Bimg + (size_t)blockIdx.x * 32768;
        const unsigned short* srcL = srcH + 16384;
#pragma unroll
        for (int i = 0; i < 8; i++) {
            int idx = i * 256 + tid;
            int row = idx >> 4, off = (idx & 15) << 4;
            *(uint4*)(sm + SM_BH + row * 272 + off) = __ldg((const uint4*)((const char*)srcH + idx * 16));
            *(uint4*)(sm + SM_BL + row * 272 + off) = __ldg((const uint4*)((const char*)srcL + idx * 16));
        }
    }
    {
        float4 br, bz, bn;
        int c4s = (tid & 31) * 4;
        if (gi) {
            br = __ldg((const float4*)(bhh + c4s));
            bz = __ldg((const float4*)(bhh + 128 + c4s));
            bn = __ldg((const float4*)(bhh + 256 + c4s));
        }
#pragma unroll 4
        for (int i = 0; i < 16; i++) {
            int row = i * 8 + (tid >> 5);
            int m = m0 + row;
            float4 v = __ldg((const float4*)(A + (size_t)m * 128 + c4s));
            if (gi) {
                const float* gm = gi + (size_t)m * 384 + c4s;
                float4 rv = __ldg((const float4*)(gm));
                float4 zv = __ldg((const float4*)(gm + 128));
                float4 nv = __ldg((const float4*)(gm + 256));
                v.x = gru_upd(v.x, rv.x, zv.x, nv.x, br.x, bz.x, bn.x);
                v.y = gru_upd(v.y, rv.y, zv.y, nv.y, br.y, bz.y, bn.y);
                v.z = gru_upd(v.z, rv.z, zv.z, nv.z, br.z, bz.z, bn.z);
                v.w = gru_upd(v.w, rv.w, zv.w, nv.w, br.w, bz.w, bn.w);
                *(float4*)(xout + (size_t)m * 128 + c4s) = v;
            }
            __nv_bfloat16 h0 = __float2bfloat16(v.x), h1 = __float2bfloat16(v.y);
            __nv_bfloat16 h2 = __float2bfloat16(v.z), h3 = __float2bfloat16(v.w);
            __nv_bfloat16 e0 = __float2bfloat16(v.x - __bfloat162float(h0));
            __nv_bfloat16 e1 = __float2bfloat16(v.y - __bfloat162float(h1));
            __nv_bfloat16 e2 = __float2bfloat16(v.z - __bfloat162float(h2));
            __nv_bfloat16 e3 = __float2bfloat16(v.w - __bfloat162float(h3));
            __nv_bfloat162 p01, p23, q01, q23;
            p01.x = h0; p01.y = h1; p23.x = h2; p23.y = h3;
            q01.x = e0; q01.y = e1; q23.x = e2; q23.y = e3;
            uint2 ph = make_uint2(*(u32*)&p01, *(u32*)&p23);
            uint2 pl = make_uint2(*(u32*)&q01, *(u32*)&q23);
            *(uint2*)(sm + SM_AH + row * 272 + c4s * 2) = ph;
            *(uint2*)(sm + SM_AL + row * 272 + c4s * 2) = pl;
        }
    }
    __syncthreads();

    float acc[2][8][4];
#pragma unroll
    for (int t = 0; t < 2; t++)
#pragma unroll
        for (int j = 0; j < 8; j++)
#pragma unroll
            for (int q = 0; q < 4; q++) acc[t][j][q] = 0.f;

#pragma unroll
    for (int ks = 0; ks < 8; ks++) {
        int kc = ks * 16 + 2 * tig;
        u32 ah[2][4], al[2][4];
#pragma unroll
        for (int t = 0; t < 2; t++) {
            int rb = wm * 32 + t * 16 + gid;
            ah[t][0] = *(const u32*)(sm + SM_AH + rb * 272 + kc * 2);
            ah[t][1] = *(const u32*)(sm + SM_AH + (rb + 8) * 272 + kc * 2);
            ah[t][2] = *(const u32*)(sm + SM_AH + rb * 272 + (kc + 8) * 2);
            ah[t][3] = *(const u32*)(sm + SM_AH + (rb + 8) * 272 + (kc + 8) * 2);
            al[t][0] = *(const u32*)(sm + SM_AL + rb * 272 + kc * 2);
            al[t][1] = *(const u32*)(sm + SM_AL + (rb + 8) * 272 + kc * 2);
            al[t][2] = *(const u32*)(sm + SM_AL + rb * 272 + (kc + 8) * 2);
            al[t][3] = *(const u32*)(sm + SM_AL + (rb + 8) * 272 + (kc + 8) * 2);
        }
#pragma unroll
        for (int j = 0; j < 8; j++) {
            int cb = wn * 64 + j * 8 + gid;
            u32 bh0 = *(const u32*)(sm + SM_BH + cb * 272 + kc * 2);
            u32 bh1 = *(const u32*)(sm + SM_BH + cb * 272 + (kc + 8) * 2);
            u32 bl0 = *(const u32*)(sm + SM_BL + cb * 272 + kc * 2);
            u32 bl1 = *(const u32*)(sm + SM_BL + cb * 272 + (kc + 8) * 2);
#pragma unroll
            for (int t = 0; t < 2; t++) {
                mma16816(acc[t][j], ah[t], bh0, bh1);
                mma16816(acc[t][j], ah[t], bl0, bl1);
                mma16816(acc[t][j], al[t], bh0, bh1);
            }
        }
    }

#pragma unroll
    for (int t = 0; t < 2; t++) {
        int r = m0 + wm * 32 + t * 16 + gid;
        float d0 = 0.f, d8 = 0.f;
        if (rp) {
            if (r < Nn)     d0 = (float)(__ldg(rp + r + 1) - __ldg(rp + r));
            if (r + 8 < Nn) d8 = (float)(__ldg(rp + r + 9) - __ldg(rp + r + 8));
        }
#pragma unroll
        for (int j = 0; j < 8; j++) {
            int c = n0 + wn * 64 + j * 8 + 2 * tig;
            float bv0 = 0.f, bv1 = 0.f, q0 = 0.f, q1 = 0.f;
            if (bias)  { bv0 = __ldg(bias + c);  bv1 = __ldg(bias + c + 1); }
            if (bias2) { q0 = __ldg(bias2 + c);  q1 = __ldg(bias2 + c + 1); }
            float2 v0 = make_float2(acc[t][j][0] + bv0 + d0 * q0,
                                    acc[t][j][1] + bv1 + d0 * q1);
            float2 v8 = make_float2(acc[t][j][2] + bv0 + d8 * q0,
                                    acc[t][j][3] + bv1 + d8 * q1);
            if (Ch) {
                *(__half2*)(Ch + (size_t)r * Nr + c) = __floats2half2_rn(v0.x, v0.y);
                *(__half2*)(Ch + (size_t)(r + 8) * Nr + c) = __floats2half2_rn(v8.x, v8.y);
            } else {
                *(float2*)(C + (size_t)r * Nr + c) = v0;
                *(float2*)(C + (size_t)(r + 8) * Nr + c) = v8;
            }
        }
    }
}

// ---------------- warp-per-node CSR edge kernel, fp16 table + fp16 y ----------------
__global__ void __launch_bounds__(128)
edge_csr(const int* __restrict__ rp, const int* __restrict__ colp,
         const float* __restrict__ dvec, const __half* __restrict__ y,
         const __half2* __restrict__ tab, float* __restrict__ S) {
    int lane = threadIdx.x & 31;
    int n = blockIdx.x * 4 + (threadIdx.x >> 5);
    if (n >= Nn) return;
    int e0 = rp[n];
    int deg = rp[n + 1] - e0;
    float a0 = 0.f, a1 = 0.f, a2 = 0.f, a3 = 0.f;
    for (int base = 0; base < deg; base += 32) {
        int cnt = min(32, deg - base);
        float u_r = 0.f; int cc_r = 0;
        if (lane < cnt) {
            u_r = __ldg(dvec + e0 + base + lane) * SCALE;
            cc_r = __ldg(colp + e0 + base + lane);
        }
        int j = 0;
        for (; j + 4 <= cnt; j += 4) {
            float u0 = __shfl_sync(~0u, u_r, j);
            float u1 = __shfl_sync(~0u, u_r, j + 1);
            float u2 = __shfl_sync(~0u, u_r, j + 2);
            float u3 = __shfl_sync(~0u, u_r, j + 3);
            int c0 = __shfl_sync(~0u, cc_r, j);
            int c1 = __shfl_sync(~0u, cc_r, j + 1);
            int c2 = __shfl_sync(~0u, cc_r, j + 2);
            int c3 = __shfl_sync(~0u, cc_r, j + 3);
            int b0i = (int)u0, b1i = (int)u1, b2i = (int)u2, b3i = (int)u3;
            float f0 = u0 - (float)b0i, f1 = u1 - (float)b1i;
            float f2 = u2 - (float)b2i, f3 = u3 - (float)b3i;
            uint4 tA = __ldg((const uint4*)(tab + (b0i << 7) + lane * 4));
            uint4 tB = __ldg((const uint4*)(tab + (b1i << 7) + lane * 4));
            uint4 tC = __ldg((const uint4*)(tab + (b2i << 7) + lane * 4));
            uint4 tD = __ldg((const uint4*)(tab + (b3i << 7) + lane * 4));
            uint2 hA = __ldg((const uint2*)(y + ((size_t)c0 << 7) + lane * 4));
            uint2 hB = __ldg((const uint2*)(y + ((size_t)c1 << 7) + lane * 4));
            uint2 hC = __ldg((const uint2*)(y + ((size_t)c2 << 7) + lane * 4));
            uint2 hD = __ldg((const uint2*)(y + ((size_t)c3 << 7) + lane * 4));
            float2 q0, q1, q2, q3, y01, y23;
            float h;
            q0 = __half22float2(*(__half2*)&tA.x);
            q1 = __half22float2(*(__half2*)&tA.y);
            q2 = __half22float2(*(__half2*)&tA.z);
            q3 = __half22float2(*(__half2*)&tA.w);
            y01 = __half22float2(*(__half2*)&hA.x);
            y23 = __half22float2(*(__half2*)&hA.y);
            h = 0.5f * (y01.x + fmaf(f0, q0.y, q0.x)); a0 += fmaf(h, tanhap(h), h);
            h = 0.5f * (y01.y + fmaf(f0, q1.y, q1.x)); a1 += fmaf(h, tanhap(h), h);
            h = 0.5f * (y23.x + fmaf(f0, q2.y, q2.x)); a2 += fmaf(h, tanhap(h), h);
            h = 0.5f * (y23.y + fmaf(f0, q3.y, q3.x)); a3 += fmaf(h, tanhap(h), h);
            q0 = __half22float2(*(__half2*)&tB.x);
            q1 = __half22float2(*(__half2*)&tB.y);
            q2 = __half22float2(*(__half2*)&tB.z);
            q3 = __half22float2(*(__half2*)&tB.w);
            y01 = __half22float2(*(__half2*)&hB.x);
            y23 = __half22float2(*(__half2*)&hB.y);
            h = 0.5f * (y01.x + fmaf(f1, q0.y, q0.x)); a0 += fmaf(h, tanhap(h), h);
            h = 0.5f * (y01.y + fmaf(f1, q1.y, q1.x)); a1 += fmaf(h, tanhap(h), h);
            h = 0.5f * (y23.x + fmaf(f1, q2.y, q2.x)); a2 += fmaf(h, tanhap(h), h);
            h = 0.5f * (y23.y + fmaf(f1, q3.y, q3.x)); a3 += fmaf(h, tanhap(h), h);
            q0 = __half22float2(*(__half2*)&tC.x);
            q1 = __half22float2(*(__half2*)&tC.y);
            q2 = __half22float2(*(__half2*)&tC.z);
            q3 = __half22float2(*(__half2*)&tC.w);
            y01 = __half22float2(*(__half2*)&hC.x);
            y23 = __half22float2(*(__half2*)&hC.y);
            h = 0.5f * (y01.x + fmaf(f2, q0.y, q0.x)); a0 += fmaf(h, tanhap(h), h);
            h = 0.5f * (y01.y + fmaf(f2, q1.y, q1.x)); a1 += fmaf(h, tanhap(h), h);
            h = 0.5f * (y23.x + fmaf(f2, q2.y, q2.x)); a2 += fmaf(h, tanhap(h), h);
            h = 0.5f * (y23.y + fmaf(f2, q3.y, q3.x)); a3 += fmaf(h, tanhap(h), h);
            q0 = __half22float2(*(__half2*)&tD.x);
            q1 = __half22float2(*(__half2*)&tD.y);
            q2 = __half22float2(*(__half2*)&tD.z);
            q3 = __half22float2(*(__half2*)&tD.w);
            y01 = __half22float2(*(__half2*)&hD.x);
            y23 = __half22float2(*(__half2*)&hD.y);
            h = 0.5f * (y01.x + fmaf(f3, q0.y, q0.x)); a0 += fmaf(h, tanhap(h), h);
            h = 0.5f * (y01.y + fmaf(f3, q1.y, q1.x)); a1 += fmaf(h, tanhap(h), h);
            h = 0.5f * (y23.x + fmaf(f3, q2.y, q2.x)); a2 += fmaf(h, tanhap(h), h);
            h = 0.5f * (y23.y + fmaf(f3, q3.y, q3.x)); a3 += fmaf(h, tanhap(h), h);
        }
        for (; j < cnt; j++) {
            float u = __shfl_sync(~0u, u_r, j);
            int cc = __shfl_sync(~0u, cc_r, j);
            int b = (int)u;
            float f = u - (float)b;
            uint4 tv = __ldg((const uint4*)(tab + (b << 7) + lane * 4));
            uint2 hv = __ldg((const uint2*)(y + ((size_t)cc << 7) + lane * 4));
            float2 q0 = __half22float2(*(__half2*)&tv.x);
            float2 q1 = __half22float2(*(__half2*)&tv.y);
            float2 q2 = __half22float2(*(__half2*)&tv.z);
            float2 q3 = __half22float2(*(__half2*)&tv.w);
            float2 y01 = __half22float2(*(__half2*)&hv.x);
            float2 y23 = __half22float2(*(__half2*)&hv.y);
            float h0 = 0.5f * (y01.x + fmaf(f, q0.y, q0.x));
            float h1 = 0.5f * (y01.y + fmaf(f, q1.y, q1.x));
            float h2 = 0.5f * (y23.x + fmaf(f, q2.y, q2.x));
            float h3 = 0.5f * (y23.y + fmaf(f, q3.y, q3.x));
            a0 += fmaf(h0, tanhap(h0), h0);
            a1 += fmaf(h1, tanhap(h1), h1);
            a2 += fmaf(h2, tanhap(h2), h2);
            a3 += fmaf(h3, tanhap(h3), h3);
        }
    }
    *(float4*)(S + ((size_t)n << 7) + lane * 4) = make_float4(a0, a1, a2, a3);
}

// ---------------- fused GRU(l=3) + LayerNorm + pooling ----------------
__global__ void __launch_bounds__(256)
ln_pool_all(const float* __restrict__ x, const float* __restrict__ gi,
            const float* __restrict__ bhh, const int* __restrict__ batch,
            const float* __restrict__ lg, const float* __restrict__ lb,
            float* __restrict__ out, float* __restrict__ sums,
            float* __restrict__ cnt, float* __restrict__ out2) {
    __shared__ int s_last;
    int warp = (blockIdx.x * blockDim.x + threadIdx.x) >> 5;
    int lane = threadIdx.x & 31;
    if (warp < Nn) {
        int ch = lane * 4;
        float4 v = __ldg((const float4*)(x + (size_t)warp * Hh + ch));
        const float* gm = gi + (size_t)warp * 384 + ch;
        float4 rv = __ldg((const float4*)(gm));
        float4 zv = __ldg((const float4*)(gm + 128));
        float4 nv = __ldg((const float4*)(gm + 256));
        float4 br = __ldg((const float4*)(bhh + ch));
        float4 bz = __ldg((const float4*)(bhh + 128 + ch));
        float4 bn = __ldg((const float4*)(bhh + 256 + ch));
        v.x = gru_upd(v.x, rv.x, zv.x, nv.x, br.x, bz.x, bn.x);
        v.y = gru_upd(v.y, rv.y, zv.y, nv.y, br.y, bz.y, bn.y);
        v.z = gru_upd(v.z, rv.z, zv.z, nv.z, br.z, bz.z, bn.z);
        v.w = gru_upd(v.w, rv.w, zv.w, nv.w, br.w, bz.w, bn.w);
        float s = v.x + v.y + v.z + v.w;
#pragma unroll
        for (int o = 16; o; o >>= 1) s += __shfl_xor_sync(~0u, s, o);
        float mu = s * (1.0f / 128.0f);
        float dx = v.x - mu, dy = v.y - mu, dz = v.z - mu, dw = v.w - mu;
        float vs = dx * dx + dy * dy + dz * dz + dw * dw;
#pragma unroll
        for (int o = 16; o; o >>= 1) vs += __shfl_xor_sync(~0u, vs, o);
        float inv = rsqrtf(vs * (1.0f / 128.0f) + 1e-5f);
        float o0 = dx * inv * lg[ch + 0] + lb[ch + 0];
        float o1 = dy * inv * lg[ch + 1] + lb[ch + 1];
        float o2 = dz * inv * lg[ch + 2] + lb[ch + 2];
        float o3 = dw * inv * lg[ch + 3] + lb[ch + 3];
        *(float4*)(out + (size_t)warp * Hh + ch) = make_float4(o0, o1, o2, o3);
        int bm = batch[warp];
        atomicAdd(&sums[bm * Hh + ch + 0], o0);
        atomicAdd(&sums[bm * Hh + ch + 1], o1);
        atomicAdd(&sums[bm * Hh + ch + 2], o2);
        atomicAdd(&sums[bm * Hh + ch + 3], o3);
        if (lane == 0) atomicAdd(&cnt[bm], 1.0f);
    }
    __syncthreads();
    if (threadIdx.x == 0) {
        __threadfence();
        int t = atomicAdd(&g_ctr, 1);
        s_last = (t == gridDim.x - 1) ? 1 : 0;
    }
    __syncthreads();
    if (s_last) {
        for (int i = threadIdx.x; i < Mm * Hh; i += blockDim.x) {
            float c = cnt[i >> 7];
            out2[i] = sums[i] / (c < 1.f ? 1.f : c);
        }
        if (threadIdx.x == 0) g_ctr = 0;
    }
}

// ---------------- host launcher ----------------
extern "C" void kernel_launch(void* const* d_in, const int* in_sizes, int n_in,
                              void* d_out, int out_size) {
    const int*   an    = (const int*)d_in[0];
    const float* pos   = (const float*)d_in[1];
    const int*   batch = (const int*)d_in[2];
    const int*   eidx  = (const int*)d_in[3];
    const float* emb   = (const float*)d_in[4];
    const float* W1    = (const float*)d_in[5];
    const float* b1    = (const float*)d_in[6];
    const float* W2    = (const float*)d_in[7];
    const float* b2    = (const float*)d_in[8];
    const float* W_ih  = (const float*)d_in[9];
    const float* b_ih  = (const float*)d_in[10];
    const float* b_hh  = (const float*)d_in[11];
    const float* ln_g  = (const float*)d_in[12];
    const float* ln_b  = (const float*)d_in[13];
    int E = in_sizes[3] / 2;
    if (E > EMAX) E = EMAX;
    const int* rowp = eidx;
    const int* colp = eidx + E;
    float* out = (float*)d_out;

    float *xp, *Sp, *gp, *dvp, *sp, *cp, *wcp, *bcp, *scrp;
    __half* yp;
    __half2* tp;
    int* rpp;
    unsigned short *iyp, *igp;
    cudaGetSymbolAddress((void**)&xp,  g_x);
    cudaGetSymbolAddress((void**)&yp,  g_y);
    cudaGetSymbolAddress((void**)&Sp,  g_S);
    cudaGetSymbolAddress((void**)&gp,  g_gi);
    cudaGetSymbolAddress((void**)&dvp, g_d);
    cudaGetSymbolAddress((void**)&rpp, g_rp);
    cudaGetSymbolAddress((void**)&sp,  g_sums);
    cudaGetSymbolAddress((void**)&cp,  g_cnt);
    cudaGetSymbolAddress((void**)&tp,  g_tabh);
    cudaGetSymbolAddress((void**)&wcp, g_Wc);
    cudaGetSymbolAddress((void**)&bcp, g_bc2);
    cudaGetSymbolAddress((void**)&iyp, g_imgY);
    cudaGetSymbolAddress((void**)&igp, g_imgG);
    cudaGetSymbolAddress((void**)&scrp, g_scr);

    static int smem_set = 0;
    if (!smem_set) {
        cudaFuncSetAttribute(mma_gemm, cudaFuncAttributeMaxDynamicSharedMemorySize, SM_MMA_TOT);
        smem_set = 1;
    }

    // 1: init x/pads + zero sums/cnt + row_ptr
    int p0n = NP * Hh + Mm * Hh + Mm + E + 1;
    prep0<<<(p0n + 255) / 256, 256>>>(an, emb, rowp, E, xp, sp, cp, rpp);
    // 2: distances + fp16 table (tiled) + bc2
    int ndb = (E + 127) / 128;
    prep1<<<ndb + (BINS / TBB) * Ll + 12, 128>>>(pos, rowp, colp, E, ndb,
                                                 W1, W_ih, b2, dvp, tp, bcp);
    // 3: Wc = W2 @ W_ih (all layers) + transposed split planes
    gemm_f2b<<<dim3(3, 1, Ll), 256>>>(W2, W_ih, wcp, 3 * Hh,
                                      Hh * Hh, Hh * 3 * Hh, Hh * 3 * Hh);
    prep2<<<dim3(16, 8), 128>>>(W1, wcp, iyp, igp);

    const int Mt = NP / 128;
    for (int l = 0; l < Ll; l++) {
        // y (fp16) = x' @ W1a + b1   (x' = x + gru(gi_{l-1}) for l>0)
        mma_gemm<<<dim3(1, Mt), 256, SM_MMA_TOT>>>(
            xp, iyp + (size_t)l * 32768, b1 + l * Hh, nullptr, nullptr,
            (l > 0) ? gp : nullptr, b_hh + (l - 1) * 3 * Hh, xp,
            nullptr, yp, Hh);
        edge_csr<<<(Nn + 3) / 4, 128>>>(rpp, colp, dvp, yp, tp + l * BINS * Hh, Sp);
        // gi (fp32) = S @ Wc + b_ih + deg (x) bc2
        mma_gemm<<<dim3(3, Mt), 256, SM_MMA_TOT>>>(
            Sp, igp + (size_t)l * 3 * 32768, b_ih + l * 3 * Hh, rpp, bcp + l * 3 * Hh,
            nullptr, nullptr, nullptr, gp, nullptr, 3 * Hh);
    }

    float* out_x = out;
    float* out_rep = out + Nn * Hh;
    if (out_size == Mm * Hh) { out_x = scrp; out_rep = out; }
    ln_pool_all<<<(Nn + 7) / 8, 256>>>(xp, gp, b_hh + 3 * 3 * Hh, batch,
                                       ln_g, ln_b, out_x, sp, cp, out_rep);
}

// round 16
// speedup vs baseline: 1.0690x; 1.0690x over previous
#include <cuda_runtime.h>
#include <cuda_bf16.h>
#include <cuda_fp16.h>
#include <math.h>

#define Hh 128
#define Rr 50
#define Ll 4
#define Nn 10000
#define Mm 64
#define NP 10112           // 79 * 128
#define EMAX 2000000
#define BINS 2048
#define SCALE ((float)BINS / 5.0f)
#define STEP (5.0f / (float)BINS)
#define TBB 64

typedef unsigned long long u64;
typedef unsigned int u32;

__device__ __forceinline__ void fma2(u64 &d, u64 a, u64 b) {
    asm("fma.rn.f32x2 %0, %1, %2, %0;" : "+l"(d) : "l"(a), "l"(b));
}
__device__ __forceinline__ u64 pack2(float lo, float hi) {
    u64 r; asm("mov.b64 %0, {%1, %2};" : "=l"(r) : "f"(lo), "f"(hi)); return r;
}
__device__ __forceinline__ void unpack2(u64 v, float &lo, float &hi) {
    asm("mov.b64 {%0, %1}, %2;" : "=f"(lo), "=f"(hi) : "l"(v));
}
__device__ __forceinline__ float tanhap(float x) {
    float r; asm("tanh.approx.f32 %0, %1;" : "=f"(r) : "f"(x)); return r;
}

__device__ __forceinline__ float gru_upd(float xo, float rv, float zv, float nv,
                                         float bhr, float bhz, float bhn) {
    float r = __fdividef(1.f, 1.f + __expf(-(rv + bhr)));
    float z = __fdividef(1.f, 1.f + __expf(-(zv + bhz)));
    float t = nv + r * bhn;
    float e = __expf(2.f * t);
    float th = 1.f - __fdividef(2.f, e + 1.f);
    return xo + (1.f - z) * th;
}

__device__ __forceinline__ void mma16816(float* d, const u32* a, u32 b0, u32 b1) {
    asm volatile(
        "mma.sync.aligned.m16n8k16.row.col.f32.bf16.bf16.f32 "
        "{%0,%1,%2,%3}, {%4,%5,%6,%7}, {%8,%9}, {%0,%1,%2,%3};"
        : "+f"(d[0]), "+f"(d[1]), "+f"(d[2]), "+f"(d[3])
        : "r"(a[0]), "r"(a[1]), "r"(a[2]), "r"(a[3]), "r"(b0), "r"(b1));
}

// ---------------- scratch ----------------
__device__ float   g_x[NP * Hh];
__device__ float   g_y[NP * Hh];
__device__ float   g_S[NP * Hh];
__device__ float   g_gi[NP * 3 * Hh];
__device__ float   g_d[EMAX];
__device__ int     g_rp[Nn + 1];
__device__ float   g_sums[Mm * Hh];
__device__ float   g_cnt[Mm];
__device__ __half2 g_tabh[Ll * BINS * Hh];
__device__ float   g_Wc[Ll * Hh * 3 * Hh];
__device__ float   g_bc2[Ll * 3 * Hh];
__device__ unsigned short g_imgY[Ll * 2 * 16384];
__device__ unsigned short g_imgG[Ll * 3 * 2 * 16384];
__device__ int     g_ctr;

// smem byte offsets for mma_gemm (row stride 272B = 136 bf16)
#define SM_AH 0
#define SM_AL 34816
#define SM_BH 69632
#define SM_BL 104448
#define SM_MMA_TOT 139264

// ---------------- prep0 ----------------
__global__ void prep0(const int* __restrict__ an, const float* __restrict__ emb,
                      const int* __restrict__ rowp, int E,
                      float* __restrict__ x, float* __restrict__ sums,
                      float* __restrict__ cnt, int* __restrict__ rp) {
    int i = blockIdx.x * blockDim.x + threadIdx.x;
    if (i < NP * Hh) {
        int n = i >> 7, ch = i & 127;
        if (n < Nn) {
            int a = an[n];
            a = a < 0 ? 0 : (a > 99 ? 99 : a);
            x[i] = emb[a * Hh + ch];
        } else {
            x[i] = 0.f;
        }
        return;
    }
    int i2 = i - NP * Hh;
    if (i2 < Mm * Hh) { sums[i2] = 0.f; return; }
    i2 -= Mm * Hh;
    if (i2 < Mm) { cnt[i2] = 0.f; return; }
    int e = i2 - Mm;
    if (e > E) return;
    if (e == 0) {
        int b = rowp[0];
        for (int r = 0; r <= b; r++) rp[r] = 0;
    } else if (e == E) {
        int a = rowp[E - 1];
        for (int r = a + 1; r <= Nn; r++) rp[r] = E;
    } else {
        int a = rowp[e - 1], b = rowp[e];
        for (int r = a + 1; r <= b; r++) rp[r] = e;
    }
}

// ---------------- prep1: distances + fp16 table (tiled) + bc2 ----------------
__global__ void prep1(const float* __restrict__ pos, const int* __restrict__ rowp,
                      const int* __restrict__ colp, int E, int ndb,
                      const float* __restrict__ W1, const float* __restrict__ W_ih,
                      const float* __restrict__ b2,
                      float* __restrict__ dv, __half2* __restrict__ tab,
                      float* __restrict__ bc2) {
    __shared__ float basis[(TBB + 1) * Rr];
    int tid = threadIdx.x;
    int blk = blockIdx.x;
    if (blk < ndb) {
        int e = blk * 128 + tid;
        if (e < E) {
            int r = rowp[e], c = colp[e];
            float dx = pos[r * 3 + 0] - pos[c * 3 + 0];
            float dy = pos[r * 3 + 1] - pos[c * 3 + 1];
            float dz = pos[r * 3 + 2] - pos[c * 3 + 2];
            dv[e] = sqrtf(dx * dx + dy * dy + dz * dz);
        }
        return;
    }
    int t = blk - ndb;
    const int TBLKS = BINS / TBB;
    if (t < TBLKS * Ll) {
        int l = t / TBLKS, bt = t - l * TBLKS;
        int bin0 = bt * TBB;
        for (int i = tid; i < (TBB + 1) * Rr; i += 128) {
            int g = i / Rr, k = i - g * Rr;
            float c = (float)k * (5.0f / 49.0f);
            float d0 = (float)(bin0 + g) * STEP - c;
            basis[i] = expf(-50.0f * d0 * d0);
        }
        __syncthreads();
        const float* W1b = W1 + l * (Hh + Rr) * Hh + Hh * Hh;
        float w[Rr];
#pragma unroll
        for (int k = 0; k < Rr; k++) w[k] = W1b[k * Hh + tid];
        float vprev = 0.f;
#pragma unroll
        for (int k = 0; k < Rr; k++) vprev += basis[k] * w[k];
        for (int g = 1; g <= TBB; g++) {
            float v = 0.f;
            const float* bs = &basis[g * Rr];
#pragma unroll
            for (int k = 0; k < Rr; k++) v += bs[k] * w[k];
            tab[((l * BINS + bin0 + g - 1) << 7) + tid] = __floats2half2_rn(vprev, v - vprev);
            vprev = v;
        }
        return;
    }
    int t2 = t - TBLKS * Ll;
    int l = t2 / 3, chunk = t2 - l * 3;
    int n = chunk * 128 + tid;
    const float* W = W_ih + l * Hh * 3 * Hh;
    const float* b = b2 + l * Hh;
    float s = 0.f;
#pragma unroll 8
    for (int k = 0; k < Hh; k++) s += b[k] * W[k * 3 * Hh + n];
    bc2[l * 3 * Hh + n] = s;
}

// ---------------- prep2: transposed split bf16 weight planes [n][k], 128 blocks ----
__global__ void prep2(const float* __restrict__ W1, const float* __restrict__ Wc,
                      unsigned short* __restrict__ imgY, unsigned short* __restrict__ imgG) {
    int b = blockIdx.x, tid = threadIdx.x;
    int k0base = blockIdx.y * 16;
    const float* src;
    int srcNr, colOff;
    unsigned short* dst;
    if (b < 4) {
        src = W1 + (size_t)b * (Hh + Rr) * Hh;
        srcNr = 128; colOff = 0;
        dst = imgY + (size_t)b * 32768;
    } else {
        int t = b - 4;
        int l = t / 3, c = t - l * 3;
        src = Wc + (size_t)l * Hh * 384;
        srcNr = 384; colOff = c * 128;
        dst = imgG + (size_t)t * 32768;
    }
    for (int k0 = k0base; k0 < k0base + 16; k0 += 8) {
        unsigned short hi[8], lo[8];
#pragma unroll
        for (int e = 0; e < 8; e++) {
            float v = src[(size_t)(k0 + e) * srcNr + colOff + tid];
            __nv_bfloat16 h = __float2bfloat16(v);
            __nv_bfloat16 l2 = __float2bfloat16(v - __bfloat162float(h));
            hi[e] = *(unsigned short*)&h;
            lo[e] = *(unsigned short*)&l2;
        }
        *(uint4*)(dst + (size_t)tid * 128 + k0) = *(uint4*)hi;
        *(uint4*)(dst + 16384 + (size_t)tid * 128 + k0) = *(uint4*)lo;
    }
}

// ---------------- f32x2 GEMM (small Wc precompute only) ----------------
__global__ void __launch_bounds__(256, 2)
gemm_f2b(const float* __restrict__ A, const float* __restrict__ B,
         float* __restrict__ C, int Nr, int aSz, int bSz, int cSz) {
    __shared__ float As[16][132];
    __shared__ float Bs[16][128];
    int tid = threadIdx.x;
    int tx = tid & 15, ty = tid >> 4;
    int m0 = blockIdx.y * 128, n0 = blockIdx.x * 128;
    const float* Ab = A + (size_t)blockIdx.z * aSz;
    const float* Bb = B + (size_t)blockIdx.z * bSz;
    float* Cb = C + (size_t)blockIdx.z * cSz;
    u64 acc[4][8] = {};
    for (int kk = 0; kk < 128; kk += 16) {
#pragma unroll
        for (int it = 0; it < 2; it++) {
            int r = (tid >> 2) + it * 64;
            int c4 = (tid & 3) << 2;
            float4 v = *(const float4*)(Ab + (size_t)(m0 + r) * 128 + kk + c4);
            As[c4 + 0][r] = v.x; As[c4 + 1][r] = v.y;
            As[c4 + 2][r] = v.z; As[c4 + 3][r] = v.w;
        }
        {
            int r = tid >> 4, c8 = (tid & 15) << 3;
            *(float4*)&Bs[r][c8]     = *(const float4*)(Bb + (size_t)(kk + r) * Nr + n0 + c8);
            *(float4*)&Bs[r][c8 + 4] = *(const float4*)(Bb + (size_t)(kk + r) * Nr + n0 + c8 + 4);
        }
        __syncthreads();
#pragma unroll
        for (int k = 0; k < 16; k++) {
            longlong2 la = *(const longlong2*)&As[k][ty * 8];
            longlong2 lb = *(const longlong2*)&As[k][ty * 8 + 4];
            float4 b0 = *(const float4*)&Bs[k][tx * 8];
            float4 b1 = *(const float4*)&Bs[k][tx * 8 + 4];
            u64 ap[4] = { (u64)la.x, (u64)la.y, (u64)lb.x, (u64)lb.y };
            u64 bp[8] = { pack2(b0.x, b0.x), pack2(b0.y, b0.y),
                          pack2(b0.z, b0.z), pack2(b0.w, b0.w),
                          pack2(b1.x, b1.x), pack2(b1.y, b1.y),
                          pack2(b1.z, b1.z), pack2(b1.w, b1.w) };
#pragma unroll
            for (int i = 0; i < 4; i++)
#pragma unroll
                for (int j = 0; j < 8; j++) fma2(acc[i][j], ap[i], bp[j]);
        }
        __syncthreads();
    }
#pragma unroll
    for (int i = 0; i < 4; i++) {
        int mA = m0 + ty * 8 + 2 * i;
        float lo[8], hi[8];
#pragma unroll
        for (int j = 0; j < 8; j++) unpack2(acc[i][j], lo[j], hi[j]);
        *(float4*)(Cb + (size_t)mA * Nr + n0 + tx * 8)     = make_float4(lo[0], lo[1], lo[2], lo[3]);
        *(float4*)(Cb + (size_t)mA * Nr + n0 + tx * 8 + 4) = make_float4(lo[4], lo[5], lo[6], lo[7]);
        *(float4*)(Cb + (size_t)(mA + 1) * Nr + n0 + tx * 8)     = make_float4(hi[0], hi[1], hi[2], hi[3]);
        *(float4*)(Cb + (size_t)(mA + 1) * Nr + n0 + tx * 8 + 4) = make_float4(hi[4], hi[5], hi[6], hi[7]);
    }
}

// ---------------- split-bf16 mma.sync GEMM, tile 128x128, fused GRU prologue --------
__global__ void __launch_bounds__(256)
mma_gemm(const float* __restrict__ A, const unsigned short* __restrict__ Bimg,
         const float* __restrict__ bias, const int* __restrict__ rp,
         const float* __restrict__ bias2,
         const float* __restrict__ gi, const float* __restrict__ bhh,
         float* __restrict__ xout, float* __restrict__ C, int Nr) {
    extern __shared__ char sm[];
    int tid = threadIdx.x;
    int lane = tid & 31, wid = tid >> 5;
    int wm = wid >> 1, wn = wid & 1;
    int gid = lane >> 2, tig = lane & 3;
    int m0 = blockIdx.y * 128, n0 = blockIdx.x * 128;

    {
        const unsigned short* srcH = Bimg + (size_t)blockIdx.x * 32768;
        const unsigned short* srcL = srcH + 16384;
#pragma unroll
        for (int i = 0; i < 8; i++) {
            int idx = i * 256 + tid;
            int row = idx >> 4, off = (idx & 15) << 4;
            *(uint4*)(sm + SM_BH + row * 272 + off) = __ldg((const uint4*)((const char*)srcH + idx * 16));
            *(uint4*)(sm + SM_BL + row * 272 + off) = __ldg((const uint4*)((const char*)srcL + idx * 16));
        }
    }
    {
        float4 br, bz, bn;
        int c4s = (tid & 31) * 4;
        if (gi) {
            br = __ldg((const float4*)(bhh + c4s));
            bz = __ldg((const float4*)(bhh + 128 + c4s));
            bn = __ldg((const float4*)(bhh + 256 + c4s));
        }
#pragma unroll 4
        for (int i = 0; i < 16; i++) {
            int row = i * 8 + (tid >> 5);
            int m = m0 + row;
            float4 v = __ldg((const float4*)(A + (size_t)m * 128 + c4s));
            if (gi) {
                const float* gm = gi + (size_t)m * 384 + c4s;
                float4 rv = __ldg((const float4*)(gm));
                float4 zv = __ldg((const float4*)(gm + 128));
                float4 nv = __ldg((const float4*)(gm + 256));
                v.x = gru_upd(v.x, rv.x, zv.x, nv.x, br.x, bz.x, bn.x);
                v.y = gru_upd(v.y, rv.y, zv.y, nv.y, br.y, bz.y, bn.y);
                v.z = gru_upd(v.z, rv.z, zv.z, nv.z, br.z, bz.z, bn.z);
                v.w = gru_upd(v.w, rv.w, zv.w, nv.w, br.w, bz.w, bn.w);
                *(float4*)(xout + (size_t)m * 128 + c4s) = v;
            }
            __nv_bfloat16 h0 = __float2bfloat16(v.x), h1 = __float2bfloat16(v.y);
            __nv_bfloat16 h2 = __float2bfloat16(v.z), h3 = __float2bfloat16(v.w);
            __nv_bfloat16 e0 = __float2bfloat16(v.x - __bfloat162float(h0));
            __nv_bfloat16 e1 = __float2bfloat16(v.y - __bfloat162float(h1));
            __nv_bfloat16 e2 = __float2bfloat16(v.z - __bfloat162float(h2));
            __nv_bfloat16 e3 = __float2bfloat16(v.w - __bfloat162float(h3));
            __nv_bfloat162 p01, p23, q01, q23;
            p01.x = h0; p01.y = h1; p23.x = h2; p23.y = h3;
            q01.x = e0; q01.y = e1; q23.x = e2; q23.y = e3;
            uint2 ph = make_uint2(*(u32*)&p01, *(u32*)&p23);
            uint2 pl = make_uint2(*(u32*)&q01, *(u32*)&q23);
            *(uint2*)(sm + SM_AH + row * 272 + c4s * 2) = ph;
            *(uint2*)(sm + SM_AL + row * 272 + c4s * 2) = pl;
        }
    }
    __syncthreads();

    float acc[2][8][4];
#pragma unroll
    for (int t = 0; t < 2; t++)
#pragma unroll
        for (int j = 0; j < 8; j++)
#pragma unroll
            for (int q = 0; q < 4; q++) acc[t][j][q] = 0.f;

#pragma unroll
    for (int ks = 0; ks < 8; ks++) {
        int kc = ks * 16 + 2 * tig;
        u32 ah[2][4], al[2][4];
#pragma unroll
        for (int t = 0; t < 2; t++) {
            int rb = wm * 32 + t * 16 + gid;
            ah[t][0] = *(const u32*)(sm + SM_AH + rb * 272 + kc * 2);
            ah[t][1] = *(const u32*)(sm + SM_AH + (rb + 8) * 272 + kc * 2);
            ah[t][2] = *(const u32*)(sm + SM_AH + rb * 272 + (kc + 8) * 2);
            ah[t][3] = *(const u32*)(sm + SM_AH + (rb + 8) * 272 + (kc + 8) * 2);
            al[t][0] = *(const u32*)(sm + SM_AL + rb * 272 + kc * 2);
            al[t][1] = *(const u32*)(sm + SM_AL + (rb + 8) * 272 + kc * 2);
            al[t][2] = *(const u32*)(sm + SM_AL + rb * 272 + (kc + 8) * 2);
            al[t][3] = *(const u32*)(sm + SM_AL + (rb + 8) * 272 + (kc + 8) * 2);
        }
#pragma unroll
        for (int j = 0; j < 8; j++) {
            int cb = wn * 64 + j * 8 + gid;
            u32 bh0 = *(const u32*)(sm + SM_BH + cb * 272 + kc * 2);
            u32 bh1 = *(const u32*)(sm + SM_BH + cb * 272 + (kc + 8) * 2);
            u32 bl0 = *(const u32*)(sm + SM_BL + cb * 272 + kc * 2);
            u32 bl1 = *(const u32*)(sm + SM_BL + cb * 272 + (kc + 8) * 2);
#pragma unroll
            for (int t = 0; t < 2; t++) {
                mma16816(acc[t][j], ah[t], bh0, bh1);
                mma16816(acc[t][j], ah[t], bl0, bl1);
                mma16816(acc[t][j], al[t], bh0, bh1);
            }
        }
    }

#pragma unroll
    for (int t = 0; t < 2; t++) {
        int r = m0 + wm * 32 + t * 16 + gid;
        float d0 = 0.f, d8 = 0.f;
        if (rp) {
            if (r < Nn)     d0 = (float)(__ldg(rp + r + 1) - __ldg(rp + r));
            if (r + 8 < Nn) d8 = (float)(__ldg(rp + r + 9) - __ldg(rp + r + 8));
        }
#pragma unroll
        for (int j = 0; j < 8; j++) {
            int c = n0 + wn * 64 + j * 8 + 2 * tig;
            float bv0 = 0.f, bv1 = 0.f, q0 = 0.f, q1 = 0.f;
            if (bias)  { bv0 = __ldg(bias + c);  bv1 = __ldg(bias + c + 1); }
            if (bias2) { q0 = __ldg(bias2 + c);  q1 = __ldg(bias2 + c + 1); }
            float2 v0 = make_float2(acc[t][j][0] + bv0 + d0 * q0,
                                    acc[t][j][1] + bv1 + d0 * q1);
            float2 v8 = make_float2(acc[t][j][2] + bv0 + d8 * q0,
                                    acc[t][j][3] + bv1 + d8 * q1);
            *(float2*)(C + (size_t)r * Nr + c) = v0;
            *(float2*)(C + (size_t)(r + 8) * Nr + c) = v8;
        }
    }
}

// ---------------- warp-per-node CSR edge kernel, fp16 tab + fp32 y,
//                  smem-staged metadata (no shfl chains) ----------------
__global__ void __launch_bounds__(128)
edge_csr(const int* __restrict__ rp, const int* __restrict__ colp,
         const float* __restrict__ dvec, const float* __restrict__ y,
         const __half2* __restrict__ tab, float* __restrict__ S) {
    __shared__ float s_u[4][32];
    __shared__ int   s_cc[4][32];
    int lane = threadIdx.x & 31;
    int w = threadIdx.x >> 5;
    int n = blockIdx.x * 4 + w;
    if (n >= Nn) return;
    int e0 = rp[n];
    int deg = rp[n + 1] - e0;
    float a0 = 0.f, a1 = 0.f, a2 = 0.f, a3 = 0.f;
    for (int base = 0; base < deg; base += 32) {
        int cnt = min(32, deg - base);
        if (lane < cnt) {
            s_u[w][lane] = __ldg(dvec + e0 + base + lane) * SCALE;
            s_cc[w][lane] = __ldg(colp + e0 + base + lane);
        }
        __syncwarp();
        int j = 0;
        for (; j + 4 <= cnt; j += 4) {
            float u0 = s_u[w][j],     u1 = s_u[w][j + 1];
            float u2 = s_u[w][j + 2], u3 = s_u[w][j + 3];
            int c0 = s_cc[w][j],      c1 = s_cc[w][j + 1];
            int c2 = s_cc[w][j + 2],  c3 = s_cc[w][j + 3];
            int b0i = (int)u0, b1i = (int)u1, b2i = (int)u2, b3i = (int)u3;
            float f0 = u0 - (float)b0i, f1 = u1 - (float)b1i;
            float f2 = u2 - (float)b2i, f3 = u3 - (float)b3i;
            uint4 tA = __ldg((const uint4*)(tab + (b0i << 7) + lane * 4));
            uint4 tB = __ldg((const uint4*)(tab + (b1i << 7) + lane * 4));
            uint4 tC = __ldg((const uint4*)(tab + (b2i << 7) + lane * 4));
            uint4 tD = __ldg((const uint4*)(tab + (b3i << 7) + lane * 4));
            float4 yA = __ldg((const float4*)(y + ((size_t)c0 << 7)) + lane);
            float4 yB = __ldg((const float4*)(y + ((size_t)c1 << 7)) + lane);
            float4 yC = __ldg((const float4*)(y + ((size_t)c2 << 7)) + lane);
            float4 yD = __ldg((const float4*)(y + ((size_t)c3 << 7)) + lane);
            float2 q0, q1, q2, q3;
            float h;
            q0 = __half22float2(*(__half2*)&tA.x);
            q1 = __half22float2(*(__half2*)&tA.y);
            q2 = __half22float2(*(__half2*)&tA.z);
            q3 = __half22float2(*(__half2*)&tA.w);
            h = 0.5f * (yA.x + fmaf(f0, q0.y, q0.x)); a0 += fmaf(h, tanhap(h), h);
            h = 0.5f * (yA.y + fmaf(f0, q1.y, q1.x)); a1 += fmaf(h, tanhap(h), h);
            h = 0.5f * (yA.z + fmaf(f0, q2.y, q2.x)); a2 += fmaf(h, tanhap(h), h);
            h = 0.5f * (yA.w + fmaf(f0, q3.y, q3.x)); a3 += fmaf(h, tanhap(h), h);
            q0 = __half22float2(*(__half2*)&tB.x);
            q1 = __half22float2(*(__half2*)&tB.y);
            q2 = __half22float2(*(__half2*)&tB.z);
            q3 = __half22float2(*(__half2*)&tB.w);
            h = 0.5f * (yB.x + fmaf(f1, q0.y, q0.x)); a0 += fmaf(h, tanhap(h), h);
            h = 0.5f * (yB.y + fmaf(f1, q1.y, q1.x)); a1 += fmaf(h, tanhap(h), h);
            h = 0.5f * (yB.z + fmaf(f1, q2.y, q2.x)); a2 += fmaf(h, tanhap(h), h);
            h = 0.5f * (yB.w + fmaf(f1, q3.y, q3.x)); a3 += fmaf(h, tanhap(h), h);
            q0 = __half22float2(*(__half2*)&tC.x);
            q1 = __half22float2(*(__half2*)&tC.y);
            q2 = __half22float2(*(__half2*)&tC.z);
            q3 = __half22float2(*(__half2*)&tC.w);
            h = 0.5f * (yC.x + fmaf(f2, q0.y, q0.x)); a0 += fmaf(h, tanhap(h), h);
            h = 0.5f * (yC.y + fmaf(f2, q1.y, q1.x)); a1 += fmaf(h, tanhap(h), h);
            h = 0.5f * (yC.z + fmaf(f2, q2.y, q2.x)); a2 += fmaf(h, tanhap(h), h);
            h = 0.5f * (yC.w + fmaf(f2, q3.y, q3.x)); a3 += fmaf(h, tanhap(h), h);
            q0 = __half22float2(*(__half2*)&tD.x);
            q1 = __half22float2(*(__half2*)&tD.y);
            q2 = __half22float2(*(__half2*)&tD.z);
            q3 = __half22float2(*(__half2*)&tD.w);
            h = 0.5f * (yD.x + fmaf(f3, q0.y, q0.x)); a0 += fmaf(h, tanhap(h), h);
            h = 0.5f * (yD.y + fmaf(f3, q1.y, q1.x)); a1 += fmaf(h, tanhap(h), h);
            h = 0.5f * (yD.z + fmaf(f3, q2.y, q2.x)); a2 += fmaf(h, tanhap(h), h);
            h = 0.5f * (yD.w + fmaf(f3, q3.y, q3.x)); a3 += fmaf(h, tanhap(h), h);
        }
        for (; j < cnt; j++) {
            float u = s_u[w][j];
            int cc = s_cc[w][j];
            int b = (int)u;
            float f = u - (float)b;
            uint4 tv = __ldg((const uint4*)(tab + (b << 7) + lane * 4));
            float4 yv = __ldg((const float4*)(y + ((size_t)cc << 7)) + lane);
            float2 q0 = __half22float2(*(__half2*)&tv.x);
            float2 q1 = __half22float2(*(__half2*)&tv.y);
            float2 q2 = __half22float2(*(__half2*)&tv.z);
            float2 q3 = __half22float2(*(__half2*)&tv.w);
            float h0 = 0.5f * (yv.x + fmaf(f, q0.y, q0.x));
            float h1 = 0.5f * (yv.y + fmaf(f, q1.y, q1.x));
            float h2 = 0.5f * (yv.z + fmaf(f, q2.y, q2.x));
            float h3 = 0.5f * (yv.w + fmaf(f, q3.y, q3.x));
            a0 += fmaf(h0, tanhap(h0), h0);
            a1 += fmaf(h1, tanhap(h1), h1);
            a2 += fmaf(h2, tanhap(h2), h2);
            a3 += fmaf(h3, tanhap(h3), h3);
        }
        __syncwarp();
    }
    *(float4*)(S + ((size_t)n << 7) + lane * 4) = make_float4(a0, a1, a2, a3);
}

// ---------------- fused GRU(l=3) + LayerNorm + pooling ----------------
__global__ void __launch_bounds__(256)
ln_pool_all(const float* __restrict__ x, const float* __restrict__ gi,
            const float* __restrict__ bhh, const int* __restrict__ batch,
            const float* __restrict__ lg, const float* __restrict__ lb,
            float* __restrict__ out, float* __restrict__ sums,
            float* __restrict__ cnt, float* __restrict__ out2) {
    __shared__ int s_last;
    int warp = (blockIdx.x * blockDim.x + threadIdx.x) >> 5;
    int lane = threadIdx.x & 31;
    if (warp < Nn) {
        int ch = lane * 4;
        float4 v = __ldg((const float4*)(x + (size_t)warp * Hh + ch));
        const float* gm = gi + (size_t)warp * 384 + ch;
        float4 rv = __ldg((const float4*)(gm));
        float4 zv = __ldg((const float4*)(gm + 128));
        float4 nv = __ldg((const float4*)(gm + 256));
        float4 br = __ldg((const float4*)(bhh + ch));
        float4 bz = __ldg((const float4*)(bhh + 128 + ch));
        float4 bn = __ldg((const float4*)(bhh + 256 + ch));
        v.x = gru_upd(v.x, rv.x, zv.x, nv.x, br.x, bz.x, bn.x);
        v.y = gru_upd(v.y, rv.y, zv.y, nv.y, br.y, bz.y, bn.y);
        v.z = gru_upd(v.z, rv.z, zv.z, nv.z, br.z, bz.z, bn.z);
        v.w = gru_upd(v.w, rv.w, zv.w, nv.w, br.w, bz.w, bn.w);
        float s = v.x + v.y + v.z + v.w;
#pragma unroll
        for (int o = 16; o; o >>= 1) s += __shfl_xor_sync(~0u, s, o);
        float mu = s * (1.0f / 128.0f);
        float dx = v.x - mu, dy = v.y - mu, dz = v.z - mu, dw = v.w - mu;
        float vs = dx * dx + dy * dy + dz * dz + dw * dw;
#pragma unroll
        for (int o = 16; o; o >>= 1) vs += __shfl_xor_sync(~0u, vs, o);
        float inv = rsqrtf(vs * (1.0f / 128.0f) + 1e-5f);
        float o0 = dx * inv * lg[ch + 0] + lb[ch + 0];
        float o1 = dy * inv * lg[ch + 1] + lb[ch + 1];
        float o2 = dz * inv * lg[ch + 2] + lb[ch + 2];
        float o3 = dw * inv * lg[ch + 3] + lb[ch + 3];
        *(float4*)(out + (size_t)warp * Hh + ch) = make_float4(o0, o1, o2, o3);
        int bm = batch[warp];
        atomicAdd(&sums[bm * Hh + ch + 0], o0);
        atomicAdd(&sums[bm * Hh + ch + 1], o1);
        atomicAdd(&sums[bm * Hh + ch + 2], o2);
        atomicAdd(&sums[bm * Hh + ch + 3], o3);
        if (lane == 0) atomicAdd(&cnt[bm], 1.0f);
    }
    __syncthreads();
    if (threadIdx.x == 0) {
        __threadfence();
        int t = atomicAdd(&g_ctr, 1);
        s_last = (t == gridDim.x - 1) ? 1 : 0;
    }
    __syncthreads();
    if (s_last) {
        for (int i = threadIdx.x; i < Mm * Hh; i += blockDim.x) {
            float c = cnt[i >> 7];
            out2[i] = sums[i] / (c < 1.f ? 1.f : c);
        }
        if (threadIdx.x == 0) g_ctr = 0;
    }
}

// ---------------- host launcher ----------------
extern "C" void kernel_launch(void* const* d_in, const int* in_sizes, int n_in,
                              void* d_out, int out_size) {
    const int*   an    = (const int*)d_in[0];
    const float* pos   = (const float*)d_in[1];
    const int*   batch = (const int*)d_in[2];
    const int*   eidx  = (const int*)d_in[3];
    const float* emb   = (const float*)d_in[4];
    const float* W1    = (const float*)d_in[5];
    const float* b1    = (const float*)d_in[6];
    const float* W2    = (const float*)d_in[7];
    const float* b2    = (const float*)d_in[8];
    const float* W_ih  = (const float*)d_in[9];
    const float* b_ih  = (const float*)d_in[10];
    const float* b_hh  = (const float*)d_in[11];
    const float* ln_g  = (const float*)d_in[12];
    const float* ln_b  = (const float*)d_in[13];
    int E = in_sizes[3] / 2;
    if (E > EMAX) E = EMAX;
    const int* rowp = eidx;
    const int* colp = eidx + E;
    float* out = (float*)d_out;

    float *xp, *yp, *Sp, *gp, *dvp, *sp, *cp, *wcp, *bcp;
    __half2* tp;
    int* rpp;
    unsigned short *iyp, *igp;
    cudaGetSymbolAddress((void**)&xp,  g_x);
    cudaGetSymbolAddress((void**)&yp,  g_y);
    cudaGetSymbolAddress((void**)&Sp,  g_S);
    cudaGetSymbolAddress((void**)&gp,  g_gi);
    cudaGetSymbolAddress((void**)&dvp, g_d);
    cudaGetSymbolAddress((void**)&rpp, g_rp);
    cudaGetSymbolAddress((void**)&sp,  g_sums);
    cudaGetSymbolAddress((void**)&cp,  g_cnt);
    cudaGetSymbolAddress((void**)&tp,  g_tabh);
    cudaGetSymbolAddress((void**)&wcp, g_Wc);
    cudaGetSymbolAddress((void**)&bcp, g_bc2);
    cudaGetSymbolAddress((void**)&iyp, g_imgY);
    cudaGetSymbolAddress((void**)&igp, g_imgG);

    static int smem_set = 0;
    if (!smem_set) {
        cudaFuncSetAttribute(mma_gemm, cudaFuncAttributeMaxDynamicSharedMemorySize, SM_MMA_TOT);
        smem_set = 1;
    }

    // 1: init x/pads + zero sums/cnt + row_ptr
    int p0n = NP * Hh + Mm * Hh + Mm + E + 1;
    prep0<<<(p0n + 255) / 256, 256>>>(an, emb, rowp, E, xp, sp, cp, rpp);
    // 2: distances + fp16 table (tiled) + bc2
    int ndb = (E + 127) / 128;
    prep1<<<ndb + (BINS / TBB) * Ll + 12, 128>>>(pos, rowp, colp, E, ndb,
                                                 W1, W_ih, b2, dvp, tp, bcp);
    // 3: Wc = W2 @ W_ih (all layers) + transposed split planes
    gemm_f2b<<<dim3(3, 1, Ll), 256>>>(W2, W_ih, wcp, 3 * Hh,
                                      Hh * Hh, Hh * 3 * Hh, Hh * 3 * Hh);
    prep2<<<dim3(16, 8), 128>>>(W1, wcp, iyp, igp);

    const int Mt = NP / 128;
    for (int l = 0; l < Ll; l++) {
        mma_gemm<<<dim3(1, Mt), 256, SM_MMA_TOT>>>(
            xp, iyp + (size_t)l * 32768, b1 + l * Hh, nullptr, nullptr,
            (l > 0) ? gp : nullptr, b_hh + (l - 1) * 3 * Hh, xp, yp, Hh);
        edge_csr<<<(Nn + 3) / 4, 128>>>(rpp, colp, dvp, yp, tp + l * BINS * Hh, Sp);
        mma_gemm<<<dim3(3, Mt), 256, SM_MMA_TOT>>>(
            Sp, igp + (size_t)l * 3 * 32768, b_ih + l * 3 * Hh, rpp, bcp + l * 3 * Hh,
            nullptr, nullptr, nullptr, gp, 3 * Hh);
    }

    float* out_x = out;
    float* out_rep = out + Nn * Hh;
    if (out_size == Mm * Hh) { out_x = yp; out_rep = out; }
    ln_pool_all<<<(Nn + 7) / 8, 256>>>(xp, gp, b_hh + 3 * 3 * Hh, batch,
                                       ln_g, ln_b, out_x, sp, cp, out_rep);
}